// round 15
// baseline (speedup 1.0000x reference)
#include <cuda_runtime.h>
#include <math.h>
#include <stdint.h>

#define Nn 32
#define Cc 128
#define Hh 48
#define Ww 48
#define Pp 2304            // H*W
#define Kk 64
#define Ss 4
#define Ll 3
#define Rr 21
#define Jj 512             // 64 score + 256 shadow + 192 app
#define MTOT (Nn*Pp)       // 73728
#define NCH 24             // P-chunks in vlad GEMM (2304/24 = 96)

#define SST 513            // score tile smem stride

// ---------------- scratch (device globals; no allocs allowed) ----------------
__device__ float g_inv[(size_t)Nn*Pp];          // 1/norm per pixel
__device__ float g_wall[Jj*Cc];                 // stacked weights [j,c] (tf32)
__device__ float g_a[(size_t)Nn*Kk*Pp];         // a * sal_pix  [n,k,p]
__device__ float g_sal[Nn*Kk*Rr];               // region sums  [n,k,r]
__device__ float g_awsum[Nn*Kk];
__device__ float g_part[(size_t)Nn*NCH*Kk*Cc];  // vlad partials
__device__ float g_nrm[Nn];

// membership helpers: which windows (per-dim) contain coordinate h
__device__ __forceinline__ void memb1(int h, int& lo, int& hi) {
  lo = (h >= 32) ? 1 : 0;
  hi = (h >= 16) ? 1 : 0;
}
__device__ __forceinline__ void memb2(int h, int& lo, int& hi) {
  lo = (h >= 19) ? ((h - 9) / 10) : 0;
  int m = (h + 1) / 10;
  hi = m > 3 ? 3 : m;
}

__device__ __forceinline__ float f2tf(float f) {
  uint32_t r; asm("cvt.rna.tf32.f32 %0, %1;" : "=r"(r) : "f"(f));
  return __uint_as_float(r);
}
#define MMA_TF32(acc, a0, a1, a2, a3, b0, b1) \
  asm volatile( \
    "mma.sync.aligned.m16n8k8.row.col.f32.tf32.tf32.f32 " \
    "{%0,%1,%2,%3}, {%4,%5,%6,%7}, {%8,%9}, {%0,%1,%2,%3};" \
    : "+f"((acc)[0]), "+f"((acc)[1]), "+f"((acc)[2]), "+f"((acc)[3]) \
    : "r"(a0), "r"(a1), "r"(a2), "r"(a3), "r"(b0), "r"(b1))

// ---------------- K0a/K0b: zero accumulators (also shifts capture slot) ------
__global__ void k_zero1() {
  int idx = blockIdx.x * 256 + threadIdx.x;
  if (idx < Nn * Kk * Rr) g_sal[idx] = 0.f;
}
__global__ void k_zero2() {
  int idx = blockIdx.x * 256 + threadIdx.x;
  if (idx < Nn * Kk) g_awsum[idx] = 0.f;
  if (idx < Nn) g_nrm[idx] = 0.f;
}

// ---------------- K2: assemble stacked weight matrix (tf32) ------------------
__global__ void k_wall(const float* __restrict__ cw, const float* __restrict__ shw,
                       const float* __restrict__ appw) {
  int idx = blockIdx.x * 256 + threadIdx.x;
  if (idx >= Jj * Cc) return;
  int j = idx >> 7, c = idx & 127;
  float v;
  if (j < 64)       v = cw[j * 128 + c];
  else if (j < 320) v = shw[(j - 64) * 128 + c];
  else              v = appw[(j - 320) * 128 + c];
  g_wall[idx] = f2tf(v);
}

// ---------------- K3: norm + tf32 GEMM + softmax/shadow + region sums --------
// Block: 32 pixels x 512 outputs, 512 threads, 2 blocks/SM.
#define ASA 132
#define BS_OFF (32 * ASA)                         // floats (4224)
#define SMEM_K3 ((BS_OFF + 512 * 36) * 4)        // 90624 B (Ssc 65664 aliases)

__global__ void __launch_bounds__(512, 2) k_gemm_epi(const float* __restrict__ x) {
  extern __shared__ float sm[];
  float* As = sm;                       // [32][132]
  float* Bs = sm + BS_OFF;              // [512][36]
  float* Ssc = sm;                      // [32][513] after GEMM (aliases As/Bs)
  __shared__ float inv_s[32];
  __shared__ float msk[32][12];

  int tid = threadIdx.x;
  int lane = tid & 31, w = tid >> 5;    // w = 0..15
  int gr = lane >> 2, gc = lane & 3;
  int jb = w * 32;
  int n = blockIdx.x / 72, p0 = (blockIdx.x % 72) * 32;

  // ---- Phase A: load raw x [32 px][128 c] transposed into As ----
  #pragma unroll
  for (int i = 0; i < 2; i++) {
    int idx = i * 512 + tid;            // 1024 float4 slots
    int c = idx >> 3, q = idx & 7;
    float4 v = *(const float4*)(x + ((size_t)n * Cc + c) * Pp + p0 + q * 4);
    As[(q * 4 + 0) * ASA + c] = v.x;
    As[(q * 4 + 1) * ASA + c] = v.y;
    As[(q * 4 + 2) * ASA + c] = v.z;
    As[(q * 4 + 3) * ASA + c] = v.w;
  }
  __syncthreads();
  // ---- per-pixel inv norm (16 threads per pixel) ----
  {
    int pp = tid >> 4, part = tid & 15;
    float s = 0.f;
    #pragma unroll
    for (int c = 0; c < 8; c++) { float v = As[pp * ASA + part + c * 16]; s += v * v; }
    s += __shfl_down_sync(0xffffffffu, s, 8);
    s += __shfl_down_sync(0xffffffffu, s, 4);
    s += __shfl_down_sync(0xffffffffu, s, 2);
    s += __shfl_down_sync(0xffffffffu, s, 1);
    if (part == 0) inv_s[pp] = 1.0f / fmaxf(sqrtf(s), 1e-12f);
  }
  __syncthreads();
  if (tid < 32) g_inv[(size_t)n * Pp + p0 + tid] = inv_s[tid];
  // ---- scale + tf32 convert in place ----
  {
    int pp = tid >> 4, part = tid & 15;
    float iv = inv_s[pp];
    #pragma unroll
    for (int i = 0; i < 8; i++) {
      int c = part * 8 + i;
      As[pp * ASA + c] = f2tf(As[pp * ASA + c] * iv);
    }
  }
  __syncthreads();

  // ---- GEMM: 4 k-chunks of 32 ----
  float acc[2][4][4];
  #pragma unroll
  for (int mf = 0; mf < 2; mf++)
    #pragma unroll
    for (int nf = 0; nf < 4; nf++)
      #pragma unroll
      for (int q = 0; q < 4; q++) acc[mf][nf][q] = 0.f;

  #pragma unroll 1
  for (int kc = 0; kc < 128; kc += 32) {
    #pragma unroll
    for (int i = 0; i < 8; i++) {
      int idx = i * 512 + tid;
      int j = idx >> 3, q = idx & 7;
      float4 v = *(const float4*)(g_wall + (size_t)j * 128 + kc + q * 4);
      *(float4*)(Bs + j * 36 + q * 4) = v;
    }
    __syncthreads();
    #pragma unroll
    for (int ks = 0; ks < 4; ks++) {
      int kb = kc + ks * 8;
      uint32_t a[2][4];
      #pragma unroll
      for (int mf = 0; mf < 2; mf++) {
        const float* ap = As + (mf * 16 + gr) * ASA + kb + gc;
        a[mf][0] = __float_as_uint(ap[0]);
        a[mf][1] = __float_as_uint(ap[8 * ASA]);
        a[mf][2] = __float_as_uint(ap[4]);
        a[mf][3] = __float_as_uint(ap[8 * ASA + 4]);
      }
      #pragma unroll
      for (int nf = 0; nf < 4; nf++) {
        const float* bp = Bs + (jb + nf * 8 + gr) * 36 + (ks * 8) + gc;
        uint32_t b0 = __float_as_uint(bp[0]);
        uint32_t b1 = __float_as_uint(bp[4]);
        #pragma unroll
        for (int mf = 0; mf < 2; mf++)
          MMA_TF32(acc[mf][nf], a[mf][0], a[mf][1], a[mf][2], a[mf][3], b0, b1);
      }
    }
    __syncthreads();
  }

  // ---- stage scores into Ssc[32][513] ----
  #pragma unroll
  for (int mf = 0; mf < 2; mf++)
    #pragma unroll
    for (int nf = 0; nf < 4; nf++) {
      int r0 = mf * 16 + gr;
      int cb = jb + nf * 8 + 2 * gc;
      Ssc[r0 * SST + cb]           = acc[mf][nf][0];
      Ssc[r0 * SST + cb + 1]       = acc[mf][nf][1];
      Ssc[(r0 + 8) * SST + cb]     = acc[mf][nf][2];
      Ssc[(r0 + 8) * SST + cb + 1] = acc[mf][nf][3];
    }
  if (tid < 32) {
    int p = p0 + tid;
    int h = p / Ww, ww = p % Ww;
    msk[tid][0] = (h < 32) ? 1.f : 0.f;
    msk[tid][1] = (h >= 16) ? 1.f : 0.f;
    msk[tid][2] = (ww < 32) ? 1.f : 0.f;
    msk[tid][3] = (ww >= 16) ? 1.f : 0.f;
    msk[tid][4] = (h < 19) ? 1.f : 0.f;
    msk[tid][5] = (h >= 9 && h < 29) ? 1.f : 0.f;
    msk[tid][6] = (h >= 19 && h < 39) ? 1.f : 0.f;
    msk[tid][7] = (h >= 29) ? 1.f : 0.f;
    msk[tid][8] = (ww < 19) ? 1.f : 0.f;
    msk[tid][9] = (ww >= 9 && ww < 29) ? 1.f : 0.f;
    msk[tid][10] = (ww >= 19 && ww < 39) ? 1.f : 0.f;
    msk[tid][11] = (ww >= 29) ? 1.f : 0.f;
  }
  __syncthreads();

  // ---- per-pixel epilogue: warp w owns pixels w*2 .. w*2+1 ----
  #pragma unroll
  for (int i = 0; i < 2; i++) {
    int pp = w * 2 + i;
    float* row = Ssc + pp * SST;
    float s1 = row[lane], s2 = row[lane + 32];
    float mx = fmaxf(s1, s2);
    #pragma unroll
    for (int o = 16; o; o >>= 1) mx = fmaxf(mx, __shfl_xor_sync(0xffffffffu, mx, o));
    float e1 = __expf(s1 - mx), e2 = __expf(s2 - mx);
    float z = e1 + e2;
    #pragma unroll
    for (int o = 16; o; o >>= 1) z += __shfl_xor_sync(0xffffffffu, z, o);
    float a1 = e1 / z, a2 = e2 / z;

    #pragma unroll
    for (int half = 0; half < 2; half++) {
      int k = lane + half * 32;
      float s = half ? s2 : s1;
      float d0 = __expf(row[64 + k * 4 + 0] - s);
      float d1 = __expf(row[64 + k * 4 + 1] - s);
      float d2 = __expf(row[64 + k * 4 + 2] - s);
      float d3 = __expf(row[64 + k * 4 + 3] - s);
      float sal = 1.0f / (1.0f + d0 + d1 + d2 + d3);
      row[k] = (half ? a2 : a1) * sal;
    }
  }
  __syncthreads();

  // ---- coalesced g_a stores: 64 k x 32 p ----
  #pragma unroll
  for (int i = 0; i < 4; i++) {
    int idx = i * 512 + tid;
    int k = idx >> 5, pp = idx & 31;
    g_a[((size_t)n * Kk + k) * Pp + p0 + pp] = Ssc[pp * SST + k];
  }

  // ---- region-sum partials -> atomicAdd g_sal ----
  if (tid < 384) {
    int jj = tid >> 1, half = tid & 1;
    int lev = jj >> 6, k = jj & 63;
    int pbeg = half * 16, pend = pbeg + 16;
    float* base = g_sal + ((size_t)n * Kk + k) * Rr;
    if (lev == 0) {
      float s = 0.f;
      for (int pp = pbeg; pp < pend; pp++)
        s += fmaxf(Ssc[pp * SST + 320 + jj], 0.f);
      atomicAdd(base + 0, s);
    } else if (lev == 1) {
      float a4[4] = {};
      for (int pp = pbeg; pp < pend; pp++) {
        float v = fmaxf(Ssc[pp * SST + 320 + jj], 0.f);
        float t0 = v * msk[pp][0], t1 = v * msk[pp][1];
        float w0 = msk[pp][2], w1 = msk[pp][3];
        a4[0] += t0 * w0; a4[1] += t0 * w1;
        a4[2] += t1 * w0; a4[3] += t1 * w1;
      }
      #pragma unroll
      for (int r = 0; r < 4; r++) atomicAdd(base + 1 + r, a4[r]);
    } else {
      float a16[16] = {};
      for (int pp = pbeg; pp < pend; pp++) {
        float v = fmaxf(Ssc[pp * SST + 320 + jj], 0.f);
        float t0 = v * msk[pp][4], t1 = v * msk[pp][5];
        float t2 = v * msk[pp][6], t3 = v * msk[pp][7];
        float w0 = msk[pp][8], w1 = msk[pp][9], w2 = msk[pp][10], w3 = msk[pp][11];
        a16[0]  += t0 * w0; a16[1]  += t0 * w1; a16[2]  += t0 * w2; a16[3]  += t0 * w3;
        a16[4]  += t1 * w0; a16[5]  += t1 * w1; a16[6]  += t1 * w2; a16[7]  += t1 * w3;
        a16[8]  += t2 * w0; a16[9]  += t2 * w1; a16[10] += t2 * w2; a16[11] += t2 * w3;
        a16[12] += t3 * w0; a16[13] += t3 * w1; a16[14] += t3 * w2; a16[15] += t3 * w3;
      }
      #pragma unroll
      for (int r = 0; r < 16; r++) atomicAdd(base + 5 + r, a16[r]);
    }
  }
}

// ---------------- K7: vlad via tf32 mma.sync (32-px tiles, single-B) --------
#define VSAL_OFF 0
#define VA_OFF   (64 * 22)                 // 1408
#define VBH_OFF  (VA_OFF + 64 * 36)        // 3712
#define SMEM_V   ((VBH_OFF + 128 * 36) * 4)  // 33280 B

__global__ void __launch_bounds__(256) k_vlad(const float* __restrict__ x) {
  extern __shared__ float sm[];
  float* salsh = sm + VSAL_OFF;          // [64][22]
  float* As    = sm + VA_OFF;            // [64][36]  aw tf32
  float* Bh    = sm + VBH_OFF;           // [128][36] xn tf32
  __shared__ unsigned char msh[8][32];
  __shared__ float iv[32];

  int tid = threadIdx.x, lane = tid & 31, w = tid >> 5;
  int gr = lane >> 2, gc = lane & 3;
  int n = blockIdx.y, chk = blockIdx.x;
  int p0base = chk * (Pp / NCH);         // 96 px per chunk

  for (int i = tid; i < 64 * 21; i += 256)
    salsh[(i / 21) * 22 + (i % 21)] = g_sal[(size_t)n * Kk * Rr + i];

  float acc[8][4];
  #pragma unroll
  for (int nf = 0; nf < 8; nf++)
    #pragma unroll
    for (int q = 0; q < 4; q++) acc[nf][q] = 0.f;
  float regsum[8] = {};

  #pragma unroll 1
  for (int t = 0; t < 3; t++) {
    int p0 = p0base + t * 32;
    __syncthreads();
    if (tid < 32) {
      int p = p0 + tid;
      iv[tid] = g_inv[(size_t)n * Pp + p];
      int h = p / Ww, wq = p % Ww;
      int a, b;
      memb1(h, a, b);  msh[0][tid] = a; msh[1][tid] = b;
      memb1(wq, a, b); msh[2][tid] = a; msh[3][tid] = b;
      memb2(h, a, b);  msh[4][tid] = a; msh[5][tid] = b;
      memb2(wq, a, b); msh[6][tid] = a; msh[7][tid] = b;
    }
    __syncthreads();
    #pragma unroll
    for (int i = 0; i < 4; i++) {
      int idx = i * 256 + tid;
      int c = idx >> 3, q = idx & 7;
      float4 v = *(const float4*)(x + ((size_t)n * Cc + c) * Pp + p0 + q * 4);
      Bh[c * 36 + q * 4 + 0] = f2tf(v.x * iv[q * 4 + 0]);
      Bh[c * 36 + q * 4 + 1] = f2tf(v.y * iv[q * 4 + 1]);
      Bh[c * 36 + q * 4 + 2] = f2tf(v.z * iv[q * 4 + 2]);
      Bh[c * 36 + q * 4 + 3] = f2tf(v.w * iv[q * 4 + 3]);
    }
    #pragma unroll
    for (int i = 0; i < 8; i++) {
      int k = i * 8 + w;
      float av = g_a[((size_t)n * Kk + k) * Pp + p0 + lane];
      const float* sk = salsh + k * 22;
      float wsum = sk[0];
      int r1l = msh[0][lane], r1h = msh[1][lane], c1l = msh[2][lane], c1h = msh[3][lane];
      int r2l = msh[4][lane], r2h = msh[5][lane], c2l = msh[6][lane], c2h = msh[7][lane];
      for (int ii = r1l; ii <= r1h; ii++)
        for (int jj = c1l; jj <= c1h; jj++) wsum += sk[1 + 2 * ii + jj];
      for (int ii = r2l; ii <= r2h; ii++)
        for (int jj = c2l; jj <= c2h; jj++) wsum += sk[5 + 4 * ii + jj];
      float aw = f2tf(av * wsum);
      As[k * 36 + lane] = aw;
      regsum[i] += aw;
    }
    __syncthreads();
    #pragma unroll
    for (int ks = 0; ks < 4; ks++) {
      int kb = ks * 8;
      const float* ap = As + ((w >> 1) * 16 + gr) * 36 + kb + gc;
      uint32_t a0 = __float_as_uint(ap[0]);
      uint32_t a1 = __float_as_uint(ap[8 * 36]);
      uint32_t a2 = __float_as_uint(ap[4]);
      uint32_t a3 = __float_as_uint(ap[8 * 36 + 4]);
      #pragma unroll
      for (int nf = 0; nf < 8; nf++) {
        int crow = (w & 1) * 64 + nf * 8 + gr;
        const float* bp = Bh + crow * 36 + kb + gc;
        MMA_TF32(acc[nf], a0, a1, a2, a3,
                 __float_as_uint(bp[0]), __float_as_uint(bp[4]));
      }
    }
  }

  float* outp = g_part + ((size_t)n * NCH + chk) * Kk * Cc;
  #pragma unroll
  for (int nf = 0; nf < 8; nf++) {
    int r = (w >> 1) * 16 + gr;
    int col = (w & 1) * 64 + nf * 8 + 2 * gc;
    outp[r * 128 + col]           = acc[nf][0];
    outp[r * 128 + col + 1]       = acc[nf][1];
    outp[(r + 8) * 128 + col]     = acc[nf][2];
    outp[(r + 8) * 128 + col + 1] = acc[nf][3];
  }
  #pragma unroll
  for (int i = 0; i < 8; i++) {
    float s = regsum[i];
    #pragma unroll
    for (int o = 16; o; o >>= 1) s += __shfl_xor_sync(0xffffffffu, s, o);
    if (lane == 0) atomicAdd(&g_awsum[n * Kk + i * 8 + w], s);
  }
}

// ---------------- K8: reduce partials, subtract centroid, intra-norm ---------
__global__ void k_fin1(const float* __restrict__ centroids,
                       const float* __restrict__ cw, float* __restrict__ out) {
  int k = blockIdx.x, n = blockIdx.y, c = threadIdx.x;   // 128 threads
  float s = 0.f;
  #pragma unroll
  for (int ch = 0; ch < NCH; ch++)
    s += g_part[(((size_t)n * NCH + ch) * Kk + k) * Cc + c];
  float v = s - centroids[k * 128 + c] * g_awsum[n * Kk + k];
  __shared__ float red[128];
  __shared__ float invs;
  red[c] = v * v; __syncthreads();
  for (int off = 64; off; off >>= 1) {
    if (c < off) red[c] += red[c + off];
    __syncthreads();
  }
  if (c == 0) invs = 1.0f / fmaxf(sqrtf(red[0]), 1e-12f);
  __syncthreads();
  float val = v * invs * cw[k];
  out[(size_t)n * (Kk * Cc) + k * 128 + c] = val;
  red[c] = val * val; __syncthreads();
  for (int off = 64; off; off >>= 1) {
    if (c < off) red[c] += red[c + off];
    __syncthreads();
  }
  if (c == 0) atomicAdd(&g_nrm[n], red[0]);
}

// ---------------- K9: global normalization ----------------------------------
__global__ void k_fin2(float* __restrict__ out) {
  int n = blockIdx.y;
  int i = blockIdx.x * 256 + threadIdx.x;
  float inv = 1.0f / fmaxf(sqrtf(g_nrm[n]), 1e-12f);
  out[(size_t)n * (Kk * Cc) + i] *= inv;
}

// ---------------- launcher ---------------------------------------------------
extern "C" void kernel_launch(void* const* d_in, const int* in_sizes, int n_in,
                              void* d_out, int out_size) {
  const float* x         = (const float*)d_in[0];  // [N,C,H,W]
  const float* centroids = (const float*)d_in[1];  // [K,C]
  const float* conv_w    = (const float*)d_in[2];  // [K,C]
  const float* shadow_w  = (const float*)d_in[3];  // [K*S,C]
  const float* app_w     = (const float*)d_in[4];  // [L,K,C]
  const float* clw       = (const float*)d_in[5];  // [K]
  float* out = (float*)d_out;

  cudaFuncSetAttribute(k_gemm_epi, cudaFuncAttributeMaxDynamicSharedMemorySize, SMEM_K3);
  cudaFuncSetAttribute(k_vlad, cudaFuncAttributeMaxDynamicSharedMemorySize, SMEM_V);

  k_zero1<<<dim3((Nn * Kk * Rr + 255) / 256), 256>>>();               // idx 0
  k_zero2<<<dim3((Nn * Kk + 255) / 256), 256>>>();                    // idx 1
  k_wall<<<dim3((Jj * Cc + 255) / 256), 256>>>(conv_w, shadow_w, app_w); // idx 2
  k_gemm_epi<<<MTOT / 32, 512, SMEM_K3>>>(x);                         // idx 3 (ncu capture)
  k_vlad<<<dim3(NCH, Nn), 256, SMEM_V>>>(x);                          // idx 4
  k_fin1<<<dim3(Kk, Nn), 128>>>(centroids, clw, out);                 // idx 5
  k_fin2<<<dim3(Kk * Cc / 256, Nn), 256>>>(out);                      // idx 6
}

// round 16
// speedup vs baseline: 1.2158x; 1.2158x over previous
#include <cuda_runtime.h>
#include <math.h>
#include <stdint.h>

#define Nn 32
#define Cc 128
#define Hh 48
#define Ww 48
#define Pp 2304            // H*W
#define Kk 64
#define Ss 4
#define Ll 3
#define Rr 21
#define Jj 512             // 64 score + 256 shadow + 192 app
#define MTOT (Nn*Pp)       // 73728
#define NCH 24             // P-chunks in vlad GEMM (2304/24 = 96)

#define SST 513            // score tile smem stride

// ---------------- scratch (device globals; no allocs allowed) ----------------
__device__ float g_inv[(size_t)Nn*Pp];          // 1/norm per pixel
__device__ float g_wall[Jj*Cc];                 // stacked weights [j,c] (tf32)
__device__ float g_a[(size_t)Nn*Kk*Pp];         // a * sal_pix  [n,k,p]
__device__ float g_sal[Nn*Kk*Rr];               // region sums  [n,k,r]
__device__ float g_awsum[Nn*Kk];
__device__ float g_part[(size_t)Nn*NCH*Kk*Cc];  // vlad partials
__device__ float g_nrm[Nn];

// membership helpers: which windows (per-dim) contain coordinate h
__device__ __forceinline__ void memb1(int h, int& lo, int& hi) {
  lo = (h >= 32) ? 1 : 0;
  hi = (h >= 16) ? 1 : 0;
}
__device__ __forceinline__ void memb2(int h, int& lo, int& hi) {
  lo = (h >= 19) ? ((h - 9) / 10) : 0;
  int m = (h + 1) / 10;
  hi = m > 3 ? 3 : m;
}

__device__ __forceinline__ float f2tf(float f) {
  uint32_t r; asm("cvt.rna.tf32.f32 %0, %1;" : "=r"(r) : "f"(f));
  return __uint_as_float(r);
}
#define MMA_TF32(acc, a0, a1, a2, a3, b0, b1) \
  asm volatile( \
    "mma.sync.aligned.m16n8k8.row.col.f32.tf32.tf32.f32 " \
    "{%0,%1,%2,%3}, {%4,%5,%6,%7}, {%8,%9}, {%0,%1,%2,%3};" \
    : "+f"((acc)[0]), "+f"((acc)[1]), "+f"((acc)[2]), "+f"((acc)[3]) \
    : "r"(a0), "r"(a1), "r"(a2), "r"(a3), "r"(b0), "r"(b1))

// ---------------- K0: zero accumulators --------------------------------------
__global__ void k_zero() {
  int idx = blockIdx.x * 256 + threadIdx.x;
  if (idx < Nn * Kk * Rr) g_sal[idx] = 0.f;
  if (idx < Nn * Kk) g_awsum[idx] = 0.f;
  if (idx < Nn) g_nrm[idx] = 0.f;
}

// ---------------- K2: assemble stacked weight matrix (tf32) ------------------
__global__ void k_wall(const float* __restrict__ cw, const float* __restrict__ shw,
                       const float* __restrict__ appw) {
  int idx = blockIdx.x * 256 + threadIdx.x;
  if (idx >= Jj * Cc) return;
  int j = idx >> 7, c = idx & 127;
  float v;
  if (j < 64)       v = cw[j * 128 + c];
  else if (j < 320) v = shw[(j - 64) * 128 + c];
  else              v = appw[(j - 320) * 128 + c];
  g_wall[idx] = f2tf(v);
}

// ---------------- K3: norm + tf32 GEMM + softmax/shadow + region sums --------
// Block: 64 pixels x 512 outputs, 1024 threads (32 warps).  [R14 config]
#define ASA 132
#define BS_OFF (64 * ASA)                         // floats (8448)
#define SMEM_K3 (64 * SST * 4)                    // 131328 B (Ssc region is max)

__global__ void __launch_bounds__(1024, 1) k_gemm_epi(const float* __restrict__ x) {
  extern __shared__ float sm[];
  float* As = sm;                       // [64][132]
  float* Bs = sm + BS_OFF;              // [512][36]
  float* Ssc = sm;                      // [64][513] after GEMM (aliases As/Bs)
  __shared__ float inv_s[64];
  __shared__ float msk[64][12];

  int tid = threadIdx.x;
  int lane = tid & 31, w = tid >> 5;    // w = 0..31
  int gr = lane >> 2, gc = lane & 3;
  int mh = (w & 1) * 32;                // pixel half base for GEMM
  int jb = (w >> 1) * 32;               // j range base (32 j's per warp)
  int n = blockIdx.x / 36, p0 = (blockIdx.x % 36) * 64;

  // ---- Phase A: load raw x [64 px][128 c] transposed into As ----
  #pragma unroll
  for (int i = 0; i < 2; i++) {
    int idx = i * 1024 + tid;           // 2048 float4 slots
    int c = idx >> 4, q = idx & 15;
    float4 v = *(const float4*)(x + ((size_t)n * Cc + c) * Pp + p0 + q * 4);
    As[(q * 4 + 0) * ASA + c] = v.x;
    As[(q * 4 + 1) * ASA + c] = v.y;
    As[(q * 4 + 2) * ASA + c] = v.z;
    As[(q * 4 + 3) * ASA + c] = v.w;
  }
  __syncthreads();
  // ---- per-pixel inv norm (16 threads per pixel) ----
  {
    int pp = tid >> 4, part = tid & 15;
    float s = 0.f;
    #pragma unroll
    for (int c = 0; c < 8; c++) { float v = As[pp * ASA + part + c * 16]; s += v * v; }
    s += __shfl_down_sync(0xffffffffu, s, 8);
    s += __shfl_down_sync(0xffffffffu, s, 4);
    s += __shfl_down_sync(0xffffffffu, s, 2);
    s += __shfl_down_sync(0xffffffffu, s, 1);
    if (part == 0) inv_s[pp] = 1.0f / fmaxf(sqrtf(s), 1e-12f);
  }
  __syncthreads();
  if (tid < 64) g_inv[(size_t)n * Pp + p0 + tid] = inv_s[tid];
  // ---- scale + tf32 convert in place ----
  {
    int pp = tid >> 4, part = tid & 15;
    float iv = inv_s[pp];
    #pragma unroll
    for (int i = 0; i < 8; i++) {
      int c = part * 8 + i;
      As[pp * ASA + c] = f2tf(As[pp * ASA + c] * iv);
    }
  }
  __syncthreads();

  // ---- GEMM: 4 k-chunks of 32 ----
  float acc[2][4][4];
  #pragma unroll
  for (int mf = 0; mf < 2; mf++)
    #pragma unroll
    for (int nf = 0; nf < 4; nf++)
      #pragma unroll
      for (int q = 0; q < 4; q++) acc[mf][nf][q] = 0.f;

  #pragma unroll 1
  for (int kc = 0; kc < 128; kc += 32) {
    #pragma unroll
    for (int i = 0; i < 4; i++) {
      int idx = i * 1024 + tid;
      int j = idx >> 3, q = idx & 7;
      float4 v = *(const float4*)(g_wall + (size_t)j * 128 + kc + q * 4);
      *(float4*)(Bs + j * 36 + q * 4) = v;
    }
    __syncthreads();
    #pragma unroll
    for (int ks = 0; ks < 4; ks++) {
      int kb = kc + ks * 8;
      uint32_t a[2][4];
      #pragma unroll
      for (int mf = 0; mf < 2; mf++) {
        const float* ap = As + (mh + mf * 16 + gr) * ASA + kb + gc;
        a[mf][0] = __float_as_uint(ap[0]);
        a[mf][1] = __float_as_uint(ap[8 * ASA]);
        a[mf][2] = __float_as_uint(ap[4]);
        a[mf][3] = __float_as_uint(ap[8 * ASA + 4]);
      }
      #pragma unroll
      for (int nf = 0; nf < 4; nf++) {
        const float* bp = Bs + (jb + nf * 8 + gr) * 36 + (ks * 8) + gc;
        uint32_t b0 = __float_as_uint(bp[0]);
        uint32_t b1 = __float_as_uint(bp[4]);
        #pragma unroll
        for (int mf = 0; mf < 2; mf++)
          MMA_TF32(acc[mf][nf], a[mf][0], a[mf][1], a[mf][2], a[mf][3], b0, b1);
      }
    }
    __syncthreads();
  }

  // ---- stage scores into Ssc[64][513] (aliases As/Bs) ----
  #pragma unroll
  for (int mf = 0; mf < 2; mf++)
    #pragma unroll
    for (int nf = 0; nf < 4; nf++) {
      int r0 = mh + mf * 16 + gr;
      int cb = jb + nf * 8 + 2 * gc;
      Ssc[r0 * SST + cb]           = acc[mf][nf][0];
      Ssc[r0 * SST + cb + 1]       = acc[mf][nf][1];
      Ssc[(r0 + 8) * SST + cb]     = acc[mf][nf][2];
      Ssc[(r0 + 8) * SST + cb + 1] = acc[mf][nf][3];
    }
  if (tid < 64) {
    int p = p0 + tid;
    int h = p / Ww, ww = p % Ww;
    msk[tid][0] = (h < 32) ? 1.f : 0.f;
    msk[tid][1] = (h >= 16) ? 1.f : 0.f;
    msk[tid][2] = (ww < 32) ? 1.f : 0.f;
    msk[tid][3] = (ww >= 16) ? 1.f : 0.f;
    msk[tid][4] = (h < 19) ? 1.f : 0.f;
    msk[tid][5] = (h >= 9 && h < 29) ? 1.f : 0.f;
    msk[tid][6] = (h >= 19 && h < 39) ? 1.f : 0.f;
    msk[tid][7] = (h >= 29) ? 1.f : 0.f;
    msk[tid][8] = (ww < 19) ? 1.f : 0.f;
    msk[tid][9] = (ww >= 9 && ww < 29) ? 1.f : 0.f;
    msk[tid][10] = (ww >= 19 && ww < 39) ? 1.f : 0.f;
    msk[tid][11] = (ww >= 29) ? 1.f : 0.f;
  }
  __syncthreads();

  // ---- per-pixel epilogue: warp w owns pixels w*2 .. w*2+1 ----
  // shadow gate: es/(es+Σexp(h-mx)) == 1/(1+Σexp(h-s))  (exact)
  #pragma unroll
  for (int i = 0; i < 2; i++) {
    int pp = w * 2 + i;
    float* row = Ssc + pp * SST;
    float s1 = row[lane], s2 = row[lane + 32];
    float mx = fmaxf(s1, s2);
    #pragma unroll
    for (int o = 16; o; o >>= 1) mx = fmaxf(mx, __shfl_xor_sync(0xffffffffu, mx, o));
    float e1 = __expf(s1 - mx), e2 = __expf(s2 - mx);
    float z = e1 + e2;
    #pragma unroll
    for (int o = 16; o; o >>= 1) z += __shfl_xor_sync(0xffffffffu, z, o);
    float a1 = e1 / z, a2 = e2 / z;

    #pragma unroll
    for (int half = 0; half < 2; half++) {
      int k = lane + half * 32;
      float s = half ? s2 : s1;
      float d0 = __expf(row[64 + k * 4 + 0] - s);
      float d1 = __expf(row[64 + k * 4 + 1] - s);
      float d2 = __expf(row[64 + k * 4 + 2] - s);
      float d3 = __expf(row[64 + k * 4 + 3] - s);
      float sal = 1.0f / (1.0f + d0 + d1 + d2 + d3);
      row[k] = (half ? a2 : a1) * sal;
    }
  }
  __syncthreads();

  // ---- coalesced g_a stores: 64 k x 64 p ----
  #pragma unroll
  for (int i = 0; i < 4; i++) {
    int idx = i * 1024 + tid;
    int k = idx >> 6, pp = idx & 63;
    g_a[((size_t)n * Kk + k) * Pp + p0 + pp] = Ssc[pp * SST + k];
  }

  // ---- region-sum partials -> atomicAdd g_sal ----
  if (tid < 384) {
    int jj = tid >> 1, half = tid & 1;
    int lev = jj >> 6, k = jj & 63;
    int pbeg = half * 32, pend = pbeg + 32;
    float* base = g_sal + ((size_t)n * Kk + k) * Rr;
    if (lev == 0) {
      float s = 0.f;
      for (int pp = pbeg; pp < pend; pp++)
        s += fmaxf(Ssc[pp * SST + 320 + jj], 0.f);
      atomicAdd(base + 0, s);
    } else if (lev == 1) {
      float a4[4] = {};
      for (int pp = pbeg; pp < pend; pp++) {
        float v = fmaxf(Ssc[pp * SST + 320 + jj], 0.f);
        float t0 = v * msk[pp][0], t1 = v * msk[pp][1];
        float w0 = msk[pp][2], w1 = msk[pp][3];
        a4[0] += t0 * w0; a4[1] += t0 * w1;
        a4[2] += t1 * w0; a4[3] += t1 * w1;
      }
      #pragma unroll
      for (int r = 0; r < 4; r++) atomicAdd(base + 1 + r, a4[r]);
    } else {
      float a16[16] = {};
      for (int pp = pbeg; pp < pend; pp++) {
        float v = fmaxf(Ssc[pp * SST + 320 + jj], 0.f);
        float t0 = v * msk[pp][4], t1 = v * msk[pp][5];
        float t2 = v * msk[pp][6], t3 = v * msk[pp][7];
        float w0 = msk[pp][8], w1 = msk[pp][9], w2 = msk[pp][10], w3 = msk[pp][11];
        a16[0]  += t0 * w0; a16[1]  += t0 * w1; a16[2]  += t0 * w2; a16[3]  += t0 * w3;
        a16[4]  += t1 * w0; a16[5]  += t1 * w1; a16[6]  += t1 * w2; a16[7]  += t1 * w3;
        a16[8]  += t2 * w0; a16[9]  += t2 * w1; a16[10] += t2 * w2; a16[11] += t2 * w3;
        a16[12] += t3 * w0; a16[13] += t3 * w1; a16[14] += t3 * w2; a16[15] += t3 * w3;
      }
      #pragma unroll
      for (int r = 0; r < 16; r++) atomicAdd(base + 5 + r, a16[r]);
    }
  }
}

// ---------------- K7: vlad via tf32 mma.sync (32-px tiles, NCH=24) ----------
#define VSAL_OFF 0
#define VA_OFF   (64 * 22)                 // 1408
#define VBH_OFF  (VA_OFF + 64 * 36)        // 3712
#define SMEM_V   ((VBH_OFF + 128 * 36) * 4)  // 33280 B

__global__ void __launch_bounds__(256) k_vlad(const float* __restrict__ x) {
  extern __shared__ float sm[];
  float* salsh = sm + VSAL_OFF;          // [64][22]
  float* As    = sm + VA_OFF;            // [64][36]  aw tf32
  float* Bh    = sm + VBH_OFF;           // [128][36] xn tf32
  __shared__ unsigned char msh[8][32];
  __shared__ float iv[32];

  int tid = threadIdx.x, lane = tid & 31, w = tid >> 5;
  int gr = lane >> 2, gc = lane & 3;
  int n = blockIdx.y, chk = blockIdx.x;
  int p0base = chk * (Pp / NCH);         // 96 px per chunk

  for (int i = tid; i < 64 * 21; i += 256)
    salsh[(i / 21) * 22 + (i % 21)] = g_sal[(size_t)n * Kk * Rr + i];

  float acc[8][4];
  #pragma unroll
  for (int nf = 0; nf < 8; nf++)
    #pragma unroll
    for (int q = 0; q < 4; q++) acc[nf][q] = 0.f;
  float regsum[8] = {};

  #pragma unroll 1
  for (int t = 0; t < 3; t++) {
    int p0 = p0base + t * 32;
    __syncthreads();
    if (tid < 32) {
      int p = p0 + tid;
      iv[tid] = g_inv[(size_t)n * Pp + p];
      int h = p / Ww, wq = p % Ww;
      int a, b;
      memb1(h, a, b);  msh[0][tid] = a; msh[1][tid] = b;
      memb1(wq, a, b); msh[2][tid] = a; msh[3][tid] = b;
      memb2(h, a, b);  msh[4][tid] = a; msh[5][tid] = b;
      memb2(wq, a, b); msh[6][tid] = a; msh[7][tid] = b;
    }
    __syncthreads();
    #pragma unroll
    for (int i = 0; i < 4; i++) {
      int idx = i * 256 + tid;
      int c = idx >> 3, q = idx & 7;
      float4 v = *(const float4*)(x + ((size_t)n * Cc + c) * Pp + p0 + q * 4);
      Bh[c * 36 + q * 4 + 0] = f2tf(v.x * iv[q * 4 + 0]);
      Bh[c * 36 + q * 4 + 1] = f2tf(v.y * iv[q * 4 + 1]);
      Bh[c * 36 + q * 4 + 2] = f2tf(v.z * iv[q * 4 + 2]);
      Bh[c * 36 + q * 4 + 3] = f2tf(v.w * iv[q * 4 + 3]);
    }
    #pragma unroll
    for (int i = 0; i < 8; i++) {
      int k = i * 8 + w;
      float av = g_a[((size_t)n * Kk + k) * Pp + p0 + lane];
      const float* sk = salsh + k * 22;
      float wsum = sk[0];
      int r1l = msh[0][lane], r1h = msh[1][lane], c1l = msh[2][lane], c1h = msh[3][lane];
      int r2l = msh[4][lane], r2h = msh[5][lane], c2l = msh[6][lane], c2h = msh[7][lane];
      for (int ii = r1l; ii <= r1h; ii++)
        for (int jj = c1l; jj <= c1h; jj++) wsum += sk[1 + 2 * ii + jj];
      for (int ii = r2l; ii <= r2h; ii++)
        for (int jj = c2l; jj <= c2h; jj++) wsum += sk[5 + 4 * ii + jj];
      float aw = f2tf(av * wsum);
      As[k * 36 + lane] = aw;
      regsum[i] += aw;
    }
    __syncthreads();
    #pragma unroll
    for (int ks = 0; ks < 4; ks++) {
      int kb = ks * 8;
      const float* ap = As + ((w >> 1) * 16 + gr) * 36 + kb + gc;
      uint32_t a0 = __float_as_uint(ap[0]);
      uint32_t a1 = __float_as_uint(ap[8 * 36]);
      uint32_t a2 = __float_as_uint(ap[4]);
      uint32_t a3 = __float_as_uint(ap[8 * 36 + 4]);
      #pragma unroll
      for (int nf = 0; nf < 8; nf++) {
        int crow = (w & 1) * 64 + nf * 8 + gr;
        const float* bp = Bh + crow * 36 + kb + gc;
        MMA_TF32(acc[nf], a0, a1, a2, a3,
                 __float_as_uint(bp[0]), __float_as_uint(bp[4]));
      }
    }
  }

  float* outp = g_part + ((size_t)n * NCH + chk) * Kk * Cc;
  #pragma unroll
  for (int nf = 0; nf < 8; nf++) {
    int r = (w >> 1) * 16 + gr;
    int col = (w & 1) * 64 + nf * 8 + 2 * gc;
    outp[r * 128 + col]           = acc[nf][0];
    outp[r * 128 + col + 1]       = acc[nf][1];
    outp[(r + 8) * 128 + col]     = acc[nf][2];
    outp[(r + 8) * 128 + col + 1] = acc[nf][3];
  }
  #pragma unroll
  for (int i = 0; i < 8; i++) {
    float s = regsum[i];
    #pragma unroll
    for (int o = 16; o; o >>= 1) s += __shfl_xor_sync(0xffffffffu, s, o);
    if (lane == 0) atomicAdd(&g_awsum[n * Kk + i * 8 + w], s);
  }
}

// ---------------- K8: reduce partials, subtract centroid, intra-norm ---------
__global__ void k_fin1(const float* __restrict__ centroids,
                       const float* __restrict__ cw, float* __restrict__ out) {
  int k = blockIdx.x, n = blockIdx.y, c = threadIdx.x;   // 128 threads
  float s = 0.f;
  #pragma unroll
  for (int ch = 0; ch < NCH; ch++)
    s += g_part[(((size_t)n * NCH + ch) * Kk + k) * Cc + c];
  float v = s - centroids[k * 128 + c] * g_awsum[n * Kk + k];
  __shared__ float red[128];
  __shared__ float invs;
  red[c] = v * v; __syncthreads();
  for (int off = 64; off; off >>= 1) {
    if (c < off) red[c] += red[c + off];
    __syncthreads();
  }
  if (c == 0) invs = 1.0f / fmaxf(sqrtf(red[0]), 1e-12f);
  __syncthreads();
  float val = v * invs * cw[k];
  out[(size_t)n * (Kk * Cc) + k * 128 + c] = val;
  red[c] = val * val; __syncthreads();
  for (int off = 64; off; off >>= 1) {
    if (c < off) red[c] += red[c + off];
    __syncthreads();
  }
  if (c == 0) atomicAdd(&g_nrm[n], red[0]);
}

// ---------------- K9: global normalization ----------------------------------
__global__ void k_fin2(float* __restrict__ out) {
  int n = blockIdx.y;
  int i = blockIdx.x * 256 + threadIdx.x;
  float inv = 1.0f / fmaxf(sqrtf(g_nrm[n]), 1e-12f);
  out[(size_t)n * (Kk * Cc) + i] *= inv;
}

// ---------------- launcher ---------------------------------------------------
extern "C" void kernel_launch(void* const* d_in, const int* in_sizes, int n_in,
                              void* d_out, int out_size) {
  const float* x         = (const float*)d_in[0];  // [N,C,H,W]
  const float* centroids = (const float*)d_in[1];  // [K,C]
  const float* conv_w    = (const float*)d_in[2];  // [K,C]
  const float* shadow_w  = (const float*)d_in[3];  // [K*S,C]
  const float* app_w     = (const float*)d_in[4];  // [L,K,C]
  const float* clw       = (const float*)d_in[5];  // [K]
  float* out = (float*)d_out;

  cudaFuncSetAttribute(k_gemm_epi, cudaFuncAttributeMaxDynamicSharedMemorySize, SMEM_K3);
  cudaFuncSetAttribute(k_vlad, cudaFuncAttributeMaxDynamicSharedMemorySize, SMEM_V);

  k_zero<<<dim3((Nn * Kk * Rr + 255) / 256), 256>>>();                // idx 0
  k_wall<<<dim3((Jj * Cc + 255) / 256), 256>>>(conv_w, shadow_w, app_w); // idx 1
  k_gemm_epi<<<MTOT / 64, 1024, SMEM_K3>>>(x);                        // idx 2
  k_vlad<<<dim3(NCH, Nn), 256, SMEM_V>>>(x);                          // idx 3 (ncu capture)
  k_fin1<<<dim3(Kk, Nn), 128>>>(centroids, clw, out);                 // idx 4
  k_fin2<<<dim3(Kk * Cc / 256, Nn), 256>>>(out);                      // idx 5
}

// round 17
// speedup vs baseline: 1.2630x; 1.0388x over previous
#include <cuda_runtime.h>
#include <math.h>
#include <stdint.h>

#define Nn 32
#define Cc 128
#define Hh 48
#define Ww 48
#define Pp 2304            // H*W
#define Kk 64
#define Ss 4
#define Ll 3
#define Rr 21
#define Jj 512             // 64 score + 256 shadow + 192 app
#define MTOT (Nn*Pp)       // 73728
#define NCH 24             // P-chunks in vlad GEMM (2304/24 = 96)

#define SST 513            // score tile smem stride

// ---------------- scratch (device globals; no allocs allowed) ----------------
__device__ float g_inv[(size_t)Nn*Pp];          // 1/norm per pixel
__device__ float g_wall[Jj*Cc];                 // stacked weights [j,c] (tf32)
__device__ float g_a[(size_t)Nn*Kk*Pp];         // a*sal_pix, then aw (tf32) [n,k,p]
__device__ float g_sal[Nn*Kk*Rr];               // region sums  [n,k,r]
__device__ float g_awsum[Nn*Kk];
__device__ float g_part[(size_t)Nn*NCH*Kk*Cc];  // vlad partials
__device__ float g_nrm[Nn];

// membership helpers: which windows (per-dim) contain coordinate h
__device__ __forceinline__ void memb1(int h, int& lo, int& hi) {
  lo = (h >= 32) ? 1 : 0;
  hi = (h >= 16) ? 1 : 0;
}
__device__ __forceinline__ void memb2(int h, int& lo, int& hi) {
  lo = (h >= 19) ? ((h - 9) / 10) : 0;
  int m = (h + 1) / 10;
  hi = m > 3 ? 3 : m;
}

__device__ __forceinline__ float f2tf(float f) {
  uint32_t r; asm("cvt.rna.tf32.f32 %0, %1;" : "=r"(r) : "f"(f));
  return __uint_as_float(r);
}
#define MMA_TF32(acc, a0, a1, a2, a3, b0, b1) \
  asm volatile( \
    "mma.sync.aligned.m16n8k8.row.col.f32.tf32.tf32.f32 " \
    "{%0,%1,%2,%3}, {%4,%5,%6,%7}, {%8,%9}, {%0,%1,%2,%3};" \
    : "+f"((acc)[0]), "+f"((acc)[1]), "+f"((acc)[2]), "+f"((acc)[3]) \
    : "r"(a0), "r"(a1), "r"(a2), "r"(a3), "r"(b0), "r"(b1))

// ---------------- K2: weights (tf32) + zero accumulators ---------------------
__global__ void k_wall(const float* __restrict__ cw, const float* __restrict__ shw,
                       const float* __restrict__ appw) {
  int idx = blockIdx.x * 256 + threadIdx.x;
  if (idx < Nn) g_nrm[idx] = 0.f;
  if (idx < Nn * Kk) g_awsum[idx] = 0.f;
  if (idx < Nn * Kk * Rr) g_sal[idx] = 0.f;
  if (idx >= Jj * Cc) return;
  int j = idx >> 7, c = idx & 127;
  float v;
  if (j < 64)       v = cw[j * 128 + c];
  else if (j < 320) v = shw[(j - 64) * 128 + c];
  else              v = appw[(j - 320) * 128 + c];
  g_wall[idx] = f2tf(v);
}

// ---------------- K3: norm + tf32 GEMM + softmax/shadow + region sums --------
// Block: 64 pixels x 512 outputs, 1024 threads (32 warps).  [R14 config]
#define ASA 132
#define BS_OFF (64 * ASA)                         // floats (8448)
#define SMEM_K3 (64 * SST * 4)                    // 131328 B (Ssc region is max)

__global__ void __launch_bounds__(1024, 1) k_gemm_epi(const float* __restrict__ x) {
  extern __shared__ float sm[];
  float* As = sm;                       // [64][132]
  float* Bs = sm + BS_OFF;              // [512][36]
  float* Ssc = sm;                      // [64][513] after GEMM (aliases As/Bs)
  __shared__ float inv_s[64];
  __shared__ float msk[64][12];

  int tid = threadIdx.x;
  int lane = tid & 31, w = tid >> 5;    // w = 0..31
  int gr = lane >> 2, gc = lane & 3;
  int mh = (w & 1) * 32;                // pixel half base for GEMM
  int jb = (w >> 1) * 32;               // j range base (32 j's per warp)
  int n = blockIdx.x / 36, p0 = (blockIdx.x % 36) * 64;

  // ---- Phase A: load raw x [64 px][128 c] transposed into As ----
  #pragma unroll
  for (int i = 0; i < 2; i++) {
    int idx = i * 1024 + tid;           // 2048 float4 slots
    int c = idx >> 4, q = idx & 15;
    float4 v = *(const float4*)(x + ((size_t)n * Cc + c) * Pp + p0 + q * 4);
    As[(q * 4 + 0) * ASA + c] = v.x;
    As[(q * 4 + 1) * ASA + c] = v.y;
    As[(q * 4 + 2) * ASA + c] = v.z;
    As[(q * 4 + 3) * ASA + c] = v.w;
  }
  __syncthreads();
  // ---- per-pixel inv norm (16 threads per pixel) ----
  {
    int pp = tid >> 4, part = tid & 15;
    float s = 0.f;
    #pragma unroll
    for (int c = 0; c < 8; c++) { float v = As[pp * ASA + part + c * 16]; s += v * v; }
    s += __shfl_down_sync(0xffffffffu, s, 8);
    s += __shfl_down_sync(0xffffffffu, s, 4);
    s += __shfl_down_sync(0xffffffffu, s, 2);
    s += __shfl_down_sync(0xffffffffu, s, 1);
    if (part == 0) inv_s[pp] = 1.0f / fmaxf(sqrtf(s), 1e-12f);
  }
  __syncthreads();
  if (tid < 64) g_inv[(size_t)n * Pp + p0 + tid] = inv_s[tid];
  // ---- scale + tf32 convert in place ----
  {
    int pp = tid >> 4, part = tid & 15;
    float iv = inv_s[pp];
    #pragma unroll
    for (int i = 0; i < 8; i++) {
      int c = part * 8 + i;
      As[pp * ASA + c] = f2tf(As[pp * ASA + c] * iv);
    }
  }
  __syncthreads();

  // ---- GEMM: 4 k-chunks of 32 ----
  float acc[2][4][4];
  #pragma unroll
  for (int mf = 0; mf < 2; mf++)
    #pragma unroll
    for (int nf = 0; nf < 4; nf++)
      #pragma unroll
      for (int q = 0; q < 4; q++) acc[mf][nf][q] = 0.f;

  #pragma unroll 1
  for (int kc = 0; kc < 128; kc += 32) {
    #pragma unroll
    for (int i = 0; i < 4; i++) {
      int idx = i * 1024 + tid;
      int j = idx >> 3, q = idx & 7;
      float4 v = *(const float4*)(g_wall + (size_t)j * 128 + kc + q * 4);
      *(float4*)(Bs + j * 36 + q * 4) = v;
    }
    __syncthreads();
    #pragma unroll
    for (int ks = 0; ks < 4; ks++) {
      int kb = kc + ks * 8;
      uint32_t a[2][4];
      #pragma unroll
      for (int mf = 0; mf < 2; mf++) {
        const float* ap = As + (mh + mf * 16 + gr) * ASA + kb + gc;
        a[mf][0] = __float_as_uint(ap[0]);
        a[mf][1] = __float_as_uint(ap[8 * ASA]);
        a[mf][2] = __float_as_uint(ap[4]);
        a[mf][3] = __float_as_uint(ap[8 * ASA + 4]);
      }
      #pragma unroll
      for (int nf = 0; nf < 4; nf++) {
        const float* bp = Bs + (jb + nf * 8 + gr) * 36 + (ks * 8) + gc;
        uint32_t b0 = __float_as_uint(bp[0]);
        uint32_t b1 = __float_as_uint(bp[4]);
        #pragma unroll
        for (int mf = 0; mf < 2; mf++)
          MMA_TF32(acc[mf][nf], a[mf][0], a[mf][1], a[mf][2], a[mf][3], b0, b1);
      }
    }
    __syncthreads();
  }

  // ---- stage scores into Ssc[64][513] (aliases As/Bs) ----
  #pragma unroll
  for (int mf = 0; mf < 2; mf++)
    #pragma unroll
    for (int nf = 0; nf < 4; nf++) {
      int r0 = mh + mf * 16 + gr;
      int cb = jb + nf * 8 + 2 * gc;
      Ssc[r0 * SST + cb]           = acc[mf][nf][0];
      Ssc[r0 * SST + cb + 1]       = acc[mf][nf][1];
      Ssc[(r0 + 8) * SST + cb]     = acc[mf][nf][2];
      Ssc[(r0 + 8) * SST + cb + 1] = acc[mf][nf][3];
    }
  if (tid < 64) {
    int p = p0 + tid;
    int h = p / Ww, ww = p % Ww;
    msk[tid][0] = (h < 32) ? 1.f : 0.f;
    msk[tid][1] = (h >= 16) ? 1.f : 0.f;
    msk[tid][2] = (ww < 32) ? 1.f : 0.f;
    msk[tid][3] = (ww >= 16) ? 1.f : 0.f;
    msk[tid][4] = (h < 19) ? 1.f : 0.f;
    msk[tid][5] = (h >= 9 && h < 29) ? 1.f : 0.f;
    msk[tid][6] = (h >= 19 && h < 39) ? 1.f : 0.f;
    msk[tid][7] = (h >= 29) ? 1.f : 0.f;
    msk[tid][8] = (ww < 19) ? 1.f : 0.f;
    msk[tid][9] = (ww >= 9 && ww < 29) ? 1.f : 0.f;
    msk[tid][10] = (ww >= 19 && ww < 39) ? 1.f : 0.f;
    msk[tid][11] = (ww >= 29) ? 1.f : 0.f;
  }
  __syncthreads();

  // ---- per-pixel epilogue: warp w owns pixels w*2 .. w*2+1 ----
  // shadow gate: es/(es+Σexp(h-mx)) == 1/(1+Σexp(h-s))  (exact)
  #pragma unroll
  for (int i = 0; i < 2; i++) {
    int pp = w * 2 + i;
    float* row = Ssc + pp * SST;
    float s1 = row[lane], s2 = row[lane + 32];
    float mx = fmaxf(s1, s2);
    #pragma unroll
    for (int o = 16; o; o >>= 1) mx = fmaxf(mx, __shfl_xor_sync(0xffffffffu, mx, o));
    float e1 = __expf(s1 - mx), e2 = __expf(s2 - mx);
    float z = e1 + e2;
    #pragma unroll
    for (int o = 16; o; o >>= 1) z += __shfl_xor_sync(0xffffffffu, z, o);
    float a1 = e1 / z, a2 = e2 / z;

    #pragma unroll
    for (int half = 0; half < 2; half++) {
      int k = lane + half * 32;
      float s = half ? s2 : s1;
      float d0 = __expf(row[64 + k * 4 + 0] - s);
      float d1 = __expf(row[64 + k * 4 + 1] - s);
      float d2 = __expf(row[64 + k * 4 + 2] - s);
      float d3 = __expf(row[64 + k * 4 + 3] - s);
      float sal = 1.0f / (1.0f + d0 + d1 + d2 + d3);
      row[k] = (half ? a2 : a1) * sal;
    }
  }
  __syncthreads();

  // ---- coalesced g_a stores: 64 k x 64 p ----
  #pragma unroll
  for (int i = 0; i < 4; i++) {
    int idx = i * 1024 + tid;
    int k = idx >> 6, pp = idx & 63;
    g_a[((size_t)n * Kk + k) * Pp + p0 + pp] = Ssc[pp * SST + k];
  }

  // ---- region-sum partials -> atomicAdd g_sal ----
  if (tid < 384) {
    int jj = tid >> 1, half = tid & 1;
    int lev = jj >> 6, k = jj & 63;
    int pbeg = half * 32, pend = pbeg + 32;
    float* base = g_sal + ((size_t)n * Kk + k) * Rr;
    if (lev == 0) {
      float s = 0.f;
      for (int pp = pbeg; pp < pend; pp++)
        s += fmaxf(Ssc[pp * SST + 320 + jj], 0.f);
      atomicAdd(base + 0, s);
    } else if (lev == 1) {
      float a4[4] = {};
      for (int pp = pbeg; pp < pend; pp++) {
        float v = fmaxf(Ssc[pp * SST + 320 + jj], 0.f);
        float t0 = v * msk[pp][0], t1 = v * msk[pp][1];
        float w0 = msk[pp][2], w1 = msk[pp][3];
        a4[0] += t0 * w0; a4[1] += t0 * w1;
        a4[2] += t1 * w0; a4[3] += t1 * w1;
      }
      #pragma unroll
      for (int r = 0; r < 4; r++) atomicAdd(base + 1 + r, a4[r]);
    } else {
      float a16[16] = {};
      for (int pp = pbeg; pp < pend; pp++) {
        float v = fmaxf(Ssc[pp * SST + 320 + jj], 0.f);
        float t0 = v * msk[pp][4], t1 = v * msk[pp][5];
        float t2 = v * msk[pp][6], t3 = v * msk[pp][7];
        float w0 = msk[pp][8], w1 = msk[pp][9], w2 = msk[pp][10], w3 = msk[pp][11];
        a16[0]  += t0 * w0; a16[1]  += t0 * w1; a16[2]  += t0 * w2; a16[3]  += t0 * w3;
        a16[4]  += t1 * w0; a16[5]  += t1 * w1; a16[6]  += t1 * w2; a16[7]  += t1 * w3;
        a16[8]  += t2 * w0; a16[9]  += t2 * w1; a16[10] += t2 * w2; a16[11] += t2 * w3;
        a16[12] += t3 * w0; a16[13] += t3 * w1; a16[14] += t3 * w2; a16[15] += t3 * w3;
      }
      #pragma unroll
      for (int r = 0; r < 16; r++) atomicAdd(base + 5 + r, a16[r]);
    }
  }
}

// ---------------- K6: apply pyramid weight to g_a in place (tf32) ------------
// g_a[k][p] := f2tf(g_a[k][p] * wsum(k,p)) — exactly what k_vlad used to do.
__global__ void __launch_bounds__(256) k_aw() {
  __shared__ float salsh[64 * 22];
  int tid = threadIdx.x;
  int n = blockIdx.y;
  int p = blockIdx.x * 256 + tid;
  for (int i = tid; i < 64 * 21; i += 256)
    salsh[(i / 21) * 22 + (i % 21)] = g_sal[(size_t)n * Kk * Rr + i];
  __syncthreads();
  int h = p / Ww, wq = p % Ww;
  int r1l, r1h, c1l, c1h, r2l, r2h, c2l, c2h;
  memb1(h, r1l, r1h); memb1(wq, c1l, c1h);
  memb2(h, r2l, r2h); memb2(wq, c2l, c2h);
  #pragma unroll 4
  for (int k = 0; k < 64; k++) {
    const float* sk = salsh + k * 22;
    float wsum = sk[0];
    for (int ii = r1l; ii <= r1h; ii++)
      for (int jj = c1l; jj <= c1h; jj++) wsum += sk[1 + 2 * ii + jj];
    for (int ii = r2l; ii <= r2h; ii++)
      for (int jj = c2l; jj <= c2h; jj++) wsum += sk[5 + 4 * ii + jj];
    size_t idx = ((size_t)n * Kk + k) * Pp + p;
    g_a[idx] = f2tf(g_a[idx] * wsum);
  }
}

// ---------------- K7: vlad via tf32 mma.sync (lean: aw preweighted) ----------
#define VA_OFF   0
#define VB_OFF   (64 * 36)                  // 2304
#define SMEM_V   ((VB_OFF + 128 * 36) * 4)  // 27648 B

__global__ void __launch_bounds__(256) k_vlad(const float* __restrict__ x) {
  extern __shared__ float sm[];
  float* As = sm + VA_OFF;               // [64][36]  aw tf32
  float* Bh = sm + VB_OFF;               // [128][36] xn tf32
  __shared__ float iv[32];

  int tid = threadIdx.x, lane = tid & 31, w = tid >> 5;
  int gr = lane >> 2, gc = lane & 3;
  int n = blockIdx.y, chk = blockIdx.x;
  int p0base = chk * (Pp / NCH);         // 96 px per chunk

  float acc[8][4];
  #pragma unroll
  for (int nf = 0; nf < 8; nf++)
    #pragma unroll
    for (int q = 0; q < 4; q++) acc[nf][q] = 0.f;
  float regsum[8] = {};

  #pragma unroll 1
  for (int t = 0; t < 3; t++) {
    int p0 = p0base + t * 32;
    __syncthreads();
    if (tid < 32) iv[tid] = g_inv[(size_t)n * Pp + p0 + tid];
    __syncthreads();
    // B tile: [c][pp] from raw x (channel-major, p-contiguous => coalesced)
    #pragma unroll
    for (int i = 0; i < 4; i++) {
      int idx = i * 256 + tid;
      int c = idx >> 3, q = idx & 7;
      float4 v = *(const float4*)(x + ((size_t)n * Cc + c) * Pp + p0 + q * 4);
      Bh[c * 36 + q * 4 + 0] = f2tf(v.x * iv[q * 4 + 0]);
      Bh[c * 36 + q * 4 + 1] = f2tf(v.y * iv[q * 4 + 1]);
      Bh[c * 36 + q * 4 + 2] = f2tf(v.z * iv[q * 4 + 2]);
      Bh[c * 36 + q * 4 + 3] = f2tf(v.w * iv[q * 4 + 3]);
    }
    // aw tile: preweighted tf32 in g_a; k = i*8 + w, pp = lane
    #pragma unroll
    for (int i = 0; i < 8; i++) {
      int k = i * 8 + w;
      float aw = g_a[((size_t)n * Kk + k) * Pp + p0 + lane];
      As[k * 36 + lane] = aw;
      regsum[i] += aw;
    }
    __syncthreads();
    // mma: warp w -> m-frag (w>>1) [16 k], c-half (w&1) [64 c]
    #pragma unroll
    for (int ks = 0; ks < 4; ks++) {
      int kb = ks * 8;
      const float* ap = As + ((w >> 1) * 16 + gr) * 36 + kb + gc;
      uint32_t a0 = __float_as_uint(ap[0]);
      uint32_t a1 = __float_as_uint(ap[8 * 36]);
      uint32_t a2 = __float_as_uint(ap[4]);
      uint32_t a3 = __float_as_uint(ap[8 * 36 + 4]);
      #pragma unroll
      for (int nf = 0; nf < 8; nf++) {
        int crow = (w & 1) * 64 + nf * 8 + gr;
        const float* bp = Bh + crow * 36 + kb + gc;
        MMA_TF32(acc[nf], a0, a1, a2, a3,
                 __float_as_uint(bp[0]), __float_as_uint(bp[4]));
      }
    }
  }

  float* outp = g_part + ((size_t)n * NCH + chk) * Kk * Cc;
  #pragma unroll
  for (int nf = 0; nf < 8; nf++) {
    int r = (w >> 1) * 16 + gr;
    int col = (w & 1) * 64 + nf * 8 + 2 * gc;
    outp[r * 128 + col]           = acc[nf][0];
    outp[r * 128 + col + 1]       = acc[nf][1];
    outp[(r + 8) * 128 + col]     = acc[nf][2];
    outp[(r + 8) * 128 + col + 1] = acc[nf][3];
  }
  #pragma unroll
  for (int i = 0; i < 8; i++) {
    float s = regsum[i];
    #pragma unroll
    for (int o = 16; o; o >>= 1) s += __shfl_xor_sync(0xffffffffu, s, o);
    if (lane == 0) atomicAdd(&g_awsum[n * Kk + i * 8 + w], s);
  }
}

// ---------------- K8: reduce partials, subtract centroid, intra-norm ---------
__global__ void k_fin1(const float* __restrict__ centroids,
                       const float* __restrict__ cw, float* __restrict__ out) {
  int k = blockIdx.x, n = blockIdx.y, c = threadIdx.x;   // 128 threads
  float s = 0.f;
  #pragma unroll
  for (int ch = 0; ch < NCH; ch++)
    s += g_part[(((size_t)n * NCH + ch) * Kk + k) * Cc + c];
  float v = s - centroids[k * 128 + c] * g_awsum[n * Kk + k];
  __shared__ float red[128];
  __shared__ float invs;
  red[c] = v * v; __syncthreads();
  for (int off = 64; off; off >>= 1) {
    if (c < off) red[c] += red[c + off];
    __syncthreads();
  }
  if (c == 0) invs = 1.0f / fmaxf(sqrtf(red[0]), 1e-12f);
  __syncthreads();
  float val = v * invs * cw[k];
  out[(size_t)n * (Kk * Cc) + k * 128 + c] = val;
  red[c] = val * val; __syncthreads();
  for (int off = 64; off; off >>= 1) {
    if (c < off) red[c] += red[c + off];
    __syncthreads();
  }
  if (c == 0) atomicAdd(&g_nrm[n], red[0]);
}

// ---------------- K9: global normalization ----------------------------------
__global__ void k_fin2(float* __restrict__ out) {
  int n = blockIdx.y;
  int i = blockIdx.x * 256 + threadIdx.x;
  float inv = 1.0f / fmaxf(sqrtf(g_nrm[n]), 1e-12f);
  out[(size_t)n * (Kk * Cc) + i] *= inv;
}

// ---------------- launcher ---------------------------------------------------
extern "C" void kernel_launch(void* const* d_in, const int* in_sizes, int n_in,
                              void* d_out, int out_size) {
  const float* x         = (const float*)d_in[0];  // [N,C,H,W]
  const float* centroids = (const float*)d_in[1];  // [K,C]
  const float* conv_w    = (const float*)d_in[2];  // [K,C]
  const float* shadow_w  = (const float*)d_in[3];  // [K*S,C]
  const float* app_w     = (const float*)d_in[4];  // [L,K,C]
  const float* clw       = (const float*)d_in[5];  // [K]
  float* out = (float*)d_out;

  cudaFuncSetAttribute(k_gemm_epi, cudaFuncAttributeMaxDynamicSharedMemorySize, SMEM_K3);
  cudaFuncSetAttribute(k_vlad, cudaFuncAttributeMaxDynamicSharedMemorySize, SMEM_V);

  k_wall<<<dim3((Jj * Cc + 255) / 256), 256>>>(conv_w, shadow_w, app_w); // idx 0
  k_gemm_epi<<<MTOT / 64, 1024, SMEM_K3>>>(x);                        // idx 1
  k_aw<<<dim3(Pp / 256, Nn), 256>>>();                                // idx 2
  k_vlad<<<dim3(NCH, Nn), 256, SMEM_V>>>(x);                          // idx 3 (ncu capture)
  k_fin1<<<dim3(Kk, Nn), 128>>>(centroids, clw, out);                 // idx 4
  k_fin2<<<dim3(Kk * Cc / 256, Nn), 256>>>(out);                      // idx 5
}